// round 4
// baseline (speedup 1.0000x reference)
#include <cuda_runtime.h>
#include <cuda_bf16.h>
#include <math.h>

#define B 256
#define D 128
#define C 100000
#define BC (B * C)

// Margin constants (double precision)
#define MARGIN 0.5
#define SCALE_F 35.0f

__device__ float g_invF[B];     // 1/||feat_b||
__device__ float g_invW[C];     // 1/||w_c||

// ---------------------------------------------------------------------------
// f32x2 helpers (packed FP32 pair ops — 2x FFMA throughput on sm_103a)
// ---------------------------------------------------------------------------
typedef unsigned long long ull;

__device__ __forceinline__ void fma2(ull& d, ull a, ull b) {
    asm("fma.rn.f32x2 %0, %1, %2, %0;" : "+l"(d) : "l"(a), "l"(b));
}
__device__ __forceinline__ void unpack2(float& lo, float& hi, ull v) {
    asm("mov.b64 {%0, %1}, %2;" : "=f"(lo), "=f"(hi) : "l"(v));
}

// ---------------------------------------------------------------------------
// Kernel 1: weight inverse norms. grid = C/8 blocks x 256 thr (8 warps, 1 class/warp)
// ---------------------------------------------------------------------------
__global__ void norms_w_kernel(const float* __restrict__ w) {
    int warp = threadIdx.x >> 5;
    int lane = threadIdx.x & 31;
    int c = blockIdx.x * 8 + warp;
    const float4 v = *reinterpret_cast<const float4*>(&w[(size_t)c * D + lane * 4]);
    float s = v.x * v.x + v.y * v.y + v.z * v.z + v.w * v.w;
    #pragma unroll
    for (int o = 16; o > 0; o >>= 1) s += __shfl_xor_sync(0xffffffffu, s, o);
    if (lane == 0) g_invW[c] = rsqrtf(s);
}

// ---------------------------------------------------------------------------
// Kernel 2: feature inverse norms. 1 block x 256 thr; warp w handles 32 rows.
// ---------------------------------------------------------------------------
__global__ void norms_f_kernel(const float* __restrict__ feat) {
    int warp = threadIdx.x >> 5;
    int lane = threadIdx.x & 31;
    for (int r = 0; r < 32; r++) {
        int row = warp * 32 + r;
        const float4 v = *reinterpret_cast<const float4*>(&feat[row * D + lane * 4]);
        float s = v.x * v.x + v.y * v.y + v.z * v.z + v.w * v.w;
        #pragma unroll
        for (int o = 16; o > 0; o >>= 1) s += __shfl_xor_sync(0xffffffffu, s, o);
        if (lane == 0) g_invF[row] = rsqrtf(s);
    }
}

// ---------------------------------------------------------------------------
// Kernel 3: main GEMM + epilogue.
// Block tile: 128 rows x 128 cols, K = 128 (full). 256 threads, 8x8 per thread.
// SMEM layout: k2-transposed float2 pairs: fs[k2][row], ws[k2][col] (64x128 each).
// Accumulators are packed f32x2 over (k even, k odd); reduced at the end.
// ---------------------------------------------------------------------------
__global__ __launch_bounds__(256, 1)
void arcface_gemm_kernel(const float* __restrict__ feat,
                         const float* __restrict__ w,
                         float* __restrict__ out) {
    extern __shared__ char smem_raw[];
    ull* fs = reinterpret_cast<ull*>(smem_raw);          // [64][128]
    ull* ws = fs + 64 * 128;                             // [64][128]

    const int tid  = threadIdx.x;
    const int warp = tid >> 5;
    const int lane = tid & 31;
    const int rbase = blockIdx.y * 128;                  // 0 or 128
    const int cbase = blockIdx.x * 128;

    // ---- stage feat tile (transpose into [k2][row]) ----
    #pragma unroll 1
    for (int it = 0; it < 16; it++) {
        int task = it * 8 + warp;            // 0..127
        int rb = task >> 5;                  // 0..3  (32-row group)
        int kb = task & 31;                  // 0..31 (4-k chunk)
        int row = rb * 32 + lane;            // 0..127 local
        float4 g = *reinterpret_cast<const float4*>(&feat[(rbase + row) * D + kb * 4]);
        *reinterpret_cast<float2*>(&fs[(2 * kb)     * 128 + row]) = make_float2(g.x, g.y);
        *reinterpret_cast<float2*>(&fs[(2 * kb + 1) * 128 + row]) = make_float2(g.z, g.w);
    }

    // ---- stage weight tile (transpose into [k2][col], zero-pad tail) ----
    #pragma unroll 1
    for (int it = 0; it < 16; it++) {
        int task = it * 8 + warp;
        int cb = task >> 5;
        int kb = task & 31;
        int col = cb * 32 + lane;            // local col
        int c = cbase + col;
        float4 g = make_float4(0.f, 0.f, 0.f, 0.f);
        if (c < C) g = *reinterpret_cast<const float4*>(&w[(size_t)c * D + kb * 4]);
        *reinterpret_cast<float2*>(&ws[(2 * kb)     * 128 + col]) = make_float2(g.x, g.y);
        *reinterpret_cast<float2*>(&ws[(2 * kb + 1) * 128 + col]) = make_float2(g.z, g.w);
    }

    __syncthreads();

    const int tx = tid & 15;                 // col group: cols tx + 16*j
    const int ty = tid >> 4;                 // row group: rows ty*8 .. ty*8+7

    ull acc[8][8];
    #pragma unroll
    for (int i = 0; i < 8; i++)
        #pragma unroll
        for (int j = 0; j < 8; j++) acc[i][j] = 0ull;

    #pragma unroll 1
    for (int k2 = 0; k2 < 64; k2++) {
        ull a[8];
        const ulonglong2* ap = reinterpret_cast<const ulonglong2*>(&fs[k2 * 128 + ty * 8]);
        #pragma unroll
        for (int i = 0; i < 4; i++) { ulonglong2 p = ap[i]; a[2*i] = p.x; a[2*i+1] = p.y; }
        ull b[8];
        #pragma unroll
        for (int j = 0; j < 8; j++) b[j] = ws[k2 * 128 + tx + 16 * j];
        #pragma unroll
        for (int i = 0; i < 8; i++)
            #pragma unroll
            for (int j = 0; j < 8; j++) fma2(acc[i][j], a[i], b[j]);
    }

    // ---- epilogue: ip, cos = ip*invF*invW, marg = 35*cos ----
    float invFv[8], invWv[8];
    #pragma unroll
    for (int i = 0; i < 8; i++) invFv[i] = g_invF[rbase + ty * 8 + i];
    #pragma unroll
    for (int j = 0; j < 8; j++) {
        int c = cbase + tx + 16 * j;
        invWv[j] = (c < C) ? g_invW[c] : 0.f;
    }

    float* out_cos = out;
    float* out_mrg = out + BC;
    float* out_ip  = out + 2 * BC;

    #pragma unroll
    for (int i = 0; i < 8; i++) {
        int row = rbase + ty * 8 + i;
        size_t rowoff = (size_t)row * C;
        #pragma unroll
        for (int j = 0; j < 8; j++) {
            int c = cbase + tx + 16 * j;
            if (c < C) {
                float lo, hi;
                unpack2(lo, hi, acc[i][j]);
                float ip = lo + hi;
                float cosv = ip * invFv[i] * invWv[j];
                out_cos[rowoff + c] = cosv;
                out_mrg[rowoff + c] = SCALE_F * cosv;
                out_ip[rowoff + c]  = ip;
            }
        }
    }
}

// ---------------------------------------------------------------------------
// Kernel 4: ground-truth margin fixup (256 entries). Detects int32 vs int64
// label buffer at runtime (all-high-words-zero => int64). Double math for
// accuracy vs the 1e-3 rel-err threshold.
// ---------------------------------------------------------------------------
__global__ void fix_gt_kernel(const int* __restrict__ lab_raw,
                              const float* __restrict__ out_cos,
                              float* __restrict__ out_mrg) {
    __shared__ int s_is64;
    int tid = threadIdx.x;
    if (tid == 0) s_is64 = 1;
    __syncthreads();
    if (tid < 128 && lab_raw[2 * tid + 1] != 0) atomicExch(&s_is64, 0);
    __syncthreads();

    int c = s_is64 ? lab_raw[2 * tid] : lab_raw[tid];
    size_t idx = (size_t)tid * C + c;
    float cg = out_cos[idx];

    double x = (double)cg;
    if (x > 1.0) x = 1.0;
    if (x < -1.0) x = -1.0;
    const double thresh = -cos(MARGIN);       // easy_margin = False branch
    double m;
    if ((double)cg > thresh) m = cos(acos(x) + MARGIN);
    else                     m = x - MARGIN * sin(MARGIN);
    out_mrg[idx] = (float)(35.0 * m);
}

// ---------------------------------------------------------------------------
extern "C" void kernel_launch(void* const* d_in, const int* in_sizes, int n_in,
                              void* d_out, int out_size) {
    const float* feat = (const float*)d_in[0];
    const float* w    = (const float*)d_in[1];
    const int*   lab  = (const int*)d_in[2];   // width detected in-kernel
    float* out = (float*)d_out;

    norms_w_kernel<<<C / 8, 256>>>(w);
    norms_f_kernel<<<1, 256>>>(feat);

    const int smem_bytes = 2 * 64 * 128 * (int)sizeof(ull);  // 128 KB
    static int attr_set = 0;
    cudaFuncSetAttribute(arcface_gemm_kernel,
                         cudaFuncAttributeMaxDynamicSharedMemorySize, smem_bytes);
    (void)attr_set;

    dim3 grid((C + 127) / 128, B / 128);
    arcface_gemm_kernel<<<grid, 256, smem_bytes>>>(feat, w, out);

    fix_gt_kernel<<<1, 256>>>(lab, out, out + BC);
}

// round 6
// speedup vs baseline: 2.0549x; 2.0549x over previous
#include <cuda_runtime.h>
#include <cuda_bf16.h>
#include <math.h>
#include <stdint.h>

#define B_ 256
#define D_ 128
#define C_ 100000
#define BC_ (B_ * C_)
#define MARGIN 0.5
#define SCALE_F 35.0f

// ---------------- device globals (scratch; no allocs allowed) ---------------
__device__ float         g_invF[B_];
__device__ __nv_bfloat16 g_fhi[B_ * D_];
__device__ __nv_bfloat16 g_flo[B_ * D_];

// ---------------- SMEM layout (bytes, dynamic) ------------------------------
#define OFF_INVF 0                    // 256 floats
#define OFF_INVW 1024                 // 128 floats
#define OFF_A_HI 2048                 // 256 rows x 256B = 64 KB
#define OFF_A_LO (OFF_A_HI + 65536)
#define OFF_B_HI (OFF_A_LO + 65536)   // 128 rows x 256B = 32 KB
#define OFF_B_LO (OFF_B_HI + 32768)
#define SMEM_TOTAL (OFF_B_LO + 32768) // 198656 B

// ---------------- PTX helpers (all portable: sm_80+, no 'a' features) -------
__device__ __forceinline__ uint32_t smem_u32(const void* p) {
    uint32_t a;
    asm("{ .reg .u64 t; cvta.to.shared.u64 t, %1; cvt.u32.u64 %0, t; }" : "=r"(a) : "l"(p));
    return a;
}
__device__ __forceinline__ void ldsm4(uint32_t* r, uint32_t addr) {
    asm volatile("ldmatrix.sync.aligned.m8n8.x4.shared.b16 {%0,%1,%2,%3}, [%4];"
                 : "=r"(r[0]), "=r"(r[1]), "=r"(r[2]), "=r"(r[3]) : "r"(addr));
}
__device__ __forceinline__ void mma_bf16(float* d, const uint32_t* a,
                                         uint32_t b0, uint32_t b1) {
    asm volatile("mma.sync.aligned.m16n8k16.row.col.f32.bf16.bf16.f32 "
                 "{%0,%1,%2,%3}, {%4,%5,%6,%7}, {%8,%9}, {%0,%1,%2,%3};"
                 : "+f"(d[0]), "+f"(d[1]), "+f"(d[2]), "+f"(d[3])
                 : "r"(a[0]), "r"(a[1]), "r"(a[2]), "r"(a[3]), "r"(b0), "r"(b1));
}

// ---------------------------------------------------------------------------
// Kernel 1: feature prep — invF + bf16 hi/lo split. 1 block x 256 threads.
// ---------------------------------------------------------------------------
__global__ void prep_feat_kernel(const float* __restrict__ feat) {
    int t = threadIdx.x;
    const float4* row = reinterpret_cast<const float4*>(feat + t * D_);
    uint2* ph = reinterpret_cast<uint2*>(g_fhi + t * D_);
    uint2* pl = reinterpret_cast<uint2*>(g_flo + t * D_);
    float s = 0.f;
    #pragma unroll
    for (int i = 0; i < 32; i++) {
        float4 v = row[i];
        s += v.x * v.x + v.y * v.y + v.z * v.z + v.w * v.w;
        __nv_bfloat162 h0 = __floats2bfloat162_rn(v.x, v.y);
        __nv_bfloat162 h1 = __floats2bfloat162_rn(v.z, v.w);
        __nv_bfloat162 l0 = __floats2bfloat162_rn(v.x - __bfloat162float(h0.x),
                                                  v.y - __bfloat162float(h0.y));
        __nv_bfloat162 l1 = __floats2bfloat162_rn(v.z - __bfloat162float(h1.x),
                                                  v.w - __bfloat162float(h1.y));
        ph[i] = make_uint2(*reinterpret_cast<uint32_t*>(&h0), *reinterpret_cast<uint32_t*>(&h1));
        pl[i] = make_uint2(*reinterpret_cast<uint32_t*>(&l0), *reinterpret_cast<uint32_t*>(&l1));
    }
    g_invF[t] = rsqrtf(s);
}

// ---------------------------------------------------------------------------
// Kernel 2: HMMA GEMM + epilogue. One CTA per 128-class tile (782 CTAs).
// D[256 batch, 128 classes] via 3 bf16-split passes, fp32 accumulation.
// 8 warps: warp grid 4(m) x 2(n); warp tile 32 rows x 64 cols; 2 batch halves.
// SMEM tiles row-major, 256B rows, 16B-chunk XOR-(row&7) swizzle.
// ---------------------------------------------------------------------------
__global__ __launch_bounds__(256, 1)
void arcface_hmma_kernel(const float* __restrict__ w, float* __restrict__ out) {
    extern __shared__ char smem[];
    const uint32_t sb = smem_u32(smem);
    const int tid = threadIdx.x, warp = tid >> 5, lane = tid & 31;
    const int wm = warp >> 1, wn = warp & 1;
    const int cbase = blockIdx.x * 128;

    // ---- stage invF -------------------------------------------------------
    *reinterpret_cast<float*>(smem + OFF_INVF + tid * 4) = g_invF[tid];

    // ---- stage feat hi/lo: thread t = batch row t, 16 chunks of 16B -------
    {
        const uint4* fh = reinterpret_cast<const uint4*>(g_fhi + tid * D_);
        const uint4* fl = reinterpret_cast<const uint4*>(g_flo + tid * D_);
        uint32_t rb = (uint32_t)tid * 256u;
        uint32_t rx = (uint32_t)(tid & 7);
        #pragma unroll
        for (int c = 0; c < 16; c++) {
            uint32_t sw = rb + (((uint32_t)c ^ rx) << 4);
            *reinterpret_cast<uint4*>(smem + OFF_A_HI + sw) = fh[c];
            *reinterpret_cast<uint4*>(smem + OFF_A_LO + sw) = fl[c];
        }
    }

    // ---- stage W tile hi/lo + per-class inv norms -------------------------
    {
        int r = tid >> 1, half = tid & 1;
        int cg = cbase + r; if (cg >= C_) cg = C_ - 1;
        const float4* wr = reinterpret_cast<const float4*>(w + (size_t)cg * D_ + half * 64);
        uint32_t rb = (uint32_t)r * 256u;
        uint32_t xr = ((uint32_t)(r & 7)) << 4;
        float s = 0.f;
        #pragma unroll
        for (int i = 0; i < 16; i++) {
            float4 v = wr[i];
            s += v.x * v.x + v.y * v.y + v.z * v.z + v.w * v.w;
            __nv_bfloat162 h0 = __floats2bfloat162_rn(v.x, v.y);
            __nv_bfloat162 h1 = __floats2bfloat162_rn(v.z, v.w);
            __nv_bfloat162 l0 = __floats2bfloat162_rn(v.x - __bfloat162float(h0.x),
                                                      v.y - __bfloat162float(h0.y));
            __nv_bfloat162 l1 = __floats2bfloat162_rn(v.z - __bfloat162float(h1.x),
                                                      v.w - __bfloat162float(h1.y));
            uint32_t off = (uint32_t)half * 128u + (uint32_t)i * 8u;
            uint32_t sw = rb + (off ^ xr);
            *reinterpret_cast<uint2*>(smem + OFF_B_HI + sw) =
                make_uint2(*reinterpret_cast<uint32_t*>(&h0), *reinterpret_cast<uint32_t*>(&h1));
            *reinterpret_cast<uint2*>(smem + OFF_B_LO + sw) =
                make_uint2(*reinterpret_cast<uint32_t*>(&l0), *reinterpret_cast<uint32_t*>(&l1));
        }
        s += __shfl_xor_sync(0xffffffffu, s, 1);
        if (half == 0) *reinterpret_cast<float*>(smem + OFF_INVW + r * 4) = rsqrtf(s);
    }

    __syncthreads();

    // ---- ldmatrix lane->address precompute --------------------------------
    // A (m16k16 frag): lanes 0-15 -> row (lane&15), k-chunk 0; lanes 16-31 -> chunk 1
    const int a_row_in = lane & 15;
    const uint32_t a_sel = (uint32_t)(lane >> 4);
    // B (two n8k16 frags): class offset within 16, and k-chunk selector
    const int b_cls_in = ((lane >> 4) << 3) | (lane & 7);
    const uint32_t b_sel = (uint32_t)((lane >> 3) & 1);

    uint32_t bOff[4], brx[4];
    #pragma unroll
    for (int j2 = 0; j2 < 4; j2++) {
        int brow = wn * 64 + j2 * 16 + b_cls_in;       // class row in B tile
        bOff[j2] = (uint32_t)brow * 256u;
        brx[j2] = (uint32_t)(brow & 7);
    }

    const int g = lane >> 2, t2 = (lane & 3) * 2;
    float* out_cos = out;
    float* out_mrg = out + BC_;
    float* out_ip  = out + 2 * BC_;

    #pragma unroll 1
    for (int h = 0; h < 2; h++) {
        uint32_t aOff[2], arx[2];
        #pragma unroll
        for (int fm = 0; fm < 2; fm++) {
            int arow = h * 128 + wm * 32 + fm * 16 + a_row_in;
            aOff[fm] = (uint32_t)arow * 256u;
            arx[fm] = (uint32_t)(arow & 7);
        }

        float d[2][8][4];
        #pragma unroll
        for (int fm = 0; fm < 2; fm++)
            #pragma unroll
            for (int jn = 0; jn < 8; jn++)
                #pragma unroll
                for (int q = 0; q < 4; q++) d[fm][jn][q] = 0.f;

        // ---- 3 accumulating passes: fh*wh, fh*wl, fl*wh -------------------
        #pragma unroll 1
        for (int pass = 0; pass < 3; pass++) {
            uint32_t Ab = sb + ((pass == 2) ? OFF_A_LO : OFF_A_HI);
            uint32_t Bb = sb + ((pass == 1) ? OFF_B_LO : OFF_B_HI);
            #pragma unroll
            for (int kk = 0; kk < 8; kk++) {
                uint32_t a[2][4];
                #pragma unroll
                for (int fm = 0; fm < 2; fm++) {
                    uint32_t chunk = (uint32_t)kk * 2u + a_sel;
                    ldsm4(a[fm], Ab + aOff[fm] + ((chunk ^ arx[fm]) << 4));
                }
                uint32_t b[4][4];
                #pragma unroll
                for (int j2 = 0; j2 < 4; j2++) {
                    uint32_t chunk = (uint32_t)kk * 2u + b_sel;
                    ldsm4(b[j2], Bb + bOff[j2] + ((chunk ^ brx[j2]) << 4));
                }
                #pragma unroll
                for (int fm = 0; fm < 2; fm++)
                    #pragma unroll
                    for (int jn = 0; jn < 8; jn++)
                        mma_bf16(d[fm][jn], a[fm],
                                 b[jn >> 1][(jn & 1) * 2],
                                 b[jn >> 1][(jn & 1) * 2 + 1]);
            }
        }

        // ---- epilogue for this half --------------------------------------
        #pragma unroll
        for (int fm = 0; fm < 2; fm++) {
            int bat0 = h * 128 + wm * 32 + fm * 16 + g;
            float if0 = *reinterpret_cast<float*>(smem + OFF_INVF + bat0 * 4);
            float if1 = *reinterpret_cast<float*>(smem + OFF_INVF + (bat0 + 8) * 4);
            size_t ro0 = (size_t)bat0 * C_;
            size_t ro1 = (size_t)(bat0 + 8) * C_;
            #pragma unroll
            for (int jn = 0; jn < 8; jn++) {
                int cl = wn * 64 + jn * 8 + t2;
                int cls = cbase + cl;
                if (cls < C_) {
                    float2 iw = *reinterpret_cast<float2*>(smem + OFF_INVW + cl * 4);
                    float ip0 = d[fm][jn][0], ip1 = d[fm][jn][1];
                    float ip2 = d[fm][jn][2], ip3 = d[fm][jn][3];
                    float c0 = ip0 * if0 * iw.x, c1 = ip1 * if0 * iw.y;
                    float c2 = ip2 * if1 * iw.x, c3 = ip3 * if1 * iw.y;
                    *reinterpret_cast<float2*>(&out_ip[ro0 + cls])  = make_float2(ip0, ip1);
                    *reinterpret_cast<float2*>(&out_ip[ro1 + cls])  = make_float2(ip2, ip3);
                    *reinterpret_cast<float2*>(&out_cos[ro0 + cls]) = make_float2(c0, c1);
                    *reinterpret_cast<float2*>(&out_cos[ro1 + cls]) = make_float2(c2, c3);
                    *reinterpret_cast<float2*>(&out_mrg[ro0 + cls]) =
                        make_float2(SCALE_F * c0, SCALE_F * c1);
                    *reinterpret_cast<float2*>(&out_mrg[ro1 + cls]) =
                        make_float2(SCALE_F * c2, SCALE_F * c3);
                }
            }
        }
    }
}

// ---------------------------------------------------------------------------
// Kernel 3: ground-truth margin fixup (256 entries). int32/int64 label detect.
// ---------------------------------------------------------------------------
__global__ void fix_gt_kernel(const int* __restrict__ lab_raw,
                              const float* __restrict__ out_cos,
                              float* __restrict__ out_mrg) {
    __shared__ int s_is64;
    int tid = threadIdx.x;
    if (tid == 0) s_is64 = 1;
    __syncthreads();
    if (tid < 128 && lab_raw[2 * tid + 1] != 0) atomicExch(&s_is64, 0);
    __syncthreads();

    int c = s_is64 ? lab_raw[2 * tid] : lab_raw[tid];
    size_t idx = (size_t)tid * C_ + c;
    float cgt = out_cos[idx];

    double x = (double)cgt;
    if (x > 1.0) x = 1.0;
    if (x < -1.0) x = -1.0;
    const double thresh = -cos(MARGIN);
    double m;
    if ((double)cgt > thresh) m = cos(acos(x) + MARGIN);
    else                      m = x - MARGIN * sin(MARGIN);
    out_mrg[idx] = (float)(35.0 * m);
}

// ---------------------------------------------------------------------------
extern "C" void kernel_launch(void* const* d_in, const int* in_sizes, int n_in,
                              void* d_out, int out_size) {
    const float* feat = (const float*)d_in[0];
    const float* w    = (const float*)d_in[1];
    const int*   lab  = (const int*)d_in[2];
    float* out = (float*)d_out;

    prep_feat_kernel<<<1, 256>>>(feat);

    cudaFuncSetAttribute(arcface_hmma_kernel,
                         cudaFuncAttributeMaxDynamicSharedMemorySize, SMEM_TOTAL);
    int ntiles = (C_ + 127) / 128;   // 782
    arcface_hmma_kernel<<<ntiles, 256, SMEM_TOTAL>>>(w, out);

    fix_gt_kernel<<<1, 256>>>(lab, out, out + BC_);
}

// round 7
// speedup vs baseline: 2.5283x; 1.2304x over previous
#include <cuda_runtime.h>
#include <cuda_fp16.h>
#include <math.h>
#include <stdint.h>

#define B_ 256
#define D_ 128
#define C_ 100000
#define BC_ (B_ * C_)
#define SCALE_F 35.0f

// ---------------- device globals (scratch; no allocs allowed) ---------------
__device__ float  g_invF[B_];
__device__ __half g_fhi[B_ * D_];
__device__ __half g_flo[B_ * D_];

// ---------------- SMEM layout (bytes, dynamic) ------------------------------
#define OFF_INVF 0                    // 256 floats
#define OFF_INVW 1024                 // 128 floats
#define OFF_A_HI 2048                 // 256 rows x 256B = 64 KB
#define OFF_A_LO (OFF_A_HI + 65536)
#define OFF_B_HI (OFF_A_LO + 65536)   // 128 rows x 256B = 32 KB
#define SMEM_TOTAL (OFF_B_HI + 32768) // 165888 B

// ---------------- PTX helpers (portable sm_80+) ------------------------------
__device__ __forceinline__ uint32_t smem_u32(const void* p) {
    uint32_t a;
    asm("{ .reg .u64 t; cvta.to.shared.u64 t, %1; cvt.u32.u64 %0, t; }" : "=r"(a) : "l"(p));
    return a;
}
__device__ __forceinline__ void ldsm4(uint32_t* r, uint32_t addr) {
    asm volatile("ldmatrix.sync.aligned.m8n8.x4.shared.b16 {%0,%1,%2,%3}, [%4];"
                 : "=r"(r[0]), "=r"(r[1]), "=r"(r[2]), "=r"(r[3]) : "r"(addr));
}
__device__ __forceinline__ void mma_f16(float* d, const uint32_t* a,
                                        uint32_t b0, uint32_t b1) {
    asm volatile("mma.sync.aligned.m16n8k16.row.col.f32.f16.f16.f32 "
                 "{%0,%1,%2,%3}, {%4,%5,%6,%7}, {%8,%9}, {%0,%1,%2,%3};"
                 : "+f"(d[0]), "+f"(d[1]), "+f"(d[2]), "+f"(d[3])
                 : "r"(a[0]), "r"(a[1]), "r"(a[2]), "r"(a[3]), "r"(b0), "r"(b1));
}

// ---------------------------------------------------------------------------
// Kernel 1: feature prep — invF + fp16 hi/lo split. 32 blocks x 256 thr,
// one warp per batch row (lane owns 4 consecutive k).
// ---------------------------------------------------------------------------
__global__ void prep_feat_kernel(const float* __restrict__ feat) {
    int warp = threadIdx.x >> 5, lane = threadIdx.x & 31;
    int row = blockIdx.x * 8 + warp;
    float4 v = *reinterpret_cast<const float4*>(&feat[row * D_ + lane * 4]);
    float s = v.x * v.x + v.y * v.y + v.z * v.z + v.w * v.w;
    #pragma unroll
    for (int o = 16; o > 0; o >>= 1) s += __shfl_xor_sync(0xffffffffu, s, o);

    __half2 h0 = __floats2half2_rn(v.x, v.y);
    __half2 h1 = __floats2half2_rn(v.z, v.w);
    __half2 l0 = __floats2half2_rn(v.x - __half2float(h0.x), v.y - __half2float(h0.y));
    __half2 l1 = __floats2half2_rn(v.z - __half2float(h1.x), v.w - __half2float(h1.y));
    *reinterpret_cast<uint2*>(&g_fhi[row * D_ + lane * 4]) =
        make_uint2(*reinterpret_cast<uint32_t*>(&h0), *reinterpret_cast<uint32_t*>(&h1));
    *reinterpret_cast<uint2*>(&g_flo[row * D_ + lane * 4]) =
        make_uint2(*reinterpret_cast<uint32_t*>(&l0), *reinterpret_cast<uint32_t*>(&l1));
    if (lane == 0) g_invF[row] = rsqrtf(s);
}

// ---------------------------------------------------------------------------
// Kernel 2: HMMA GEMM + epilogue. One CTA per 128-class tile (782 CTAs).
// D[256 batch, 128 classes] = (fh + fl) x wh^T, fp32 accum, 2 passes.
// 8 warps in 4(m) x 2(n) grid; warp tile 64 x 64; d[4][8][4] accumulators.
// SMEM row-major 256B rows, 16B-chunk XOR-(row&7) swizzle.
// ---------------------------------------------------------------------------
__global__ __launch_bounds__(256, 1)
void arcface_hmma_kernel(const float* __restrict__ w, float* __restrict__ out) {
    extern __shared__ char smem[];
    const uint32_t sb = smem_u32(smem);
    const int tid = threadIdx.x, warp = tid >> 5, lane = tid & 31;
    const int wm = warp >> 1, wn = warp & 1;
    const int cbase = blockIdx.x * 128;

    // ---- stage invF -------------------------------------------------------
    *reinterpret_cast<float*>(smem + OFF_INVF + tid * 4) = g_invF[tid];

    // ---- stage feat hi/lo: thread t = batch row t, 16 x 16B chunks --------
    {
        const uint4* fh = reinterpret_cast<const uint4*>(g_fhi + tid * D_);
        const uint4* fl = reinterpret_cast<const uint4*>(g_flo + tid * D_);
        uint32_t rb = (uint32_t)tid * 256u;
        uint32_t rx = (uint32_t)(tid & 7);
        #pragma unroll
        for (int c = 0; c < 16; c++) {
            uint32_t sw = rb + (((uint32_t)c ^ rx) << 4);
            *reinterpret_cast<uint4*>(smem + OFF_A_HI + sw) = fh[c];
            *reinterpret_cast<uint4*>(smem + OFF_A_LO + sw) = fl[c];
        }
    }

    // ---- stage W tile (fp16 hi only) + per-class inv norms ----------------
    {
        int r = tid >> 1, half = tid & 1;
        int cg = cbase + r; if (cg >= C_) cg = C_ - 1;
        const float4* wr = reinterpret_cast<const float4*>(w + (size_t)cg * D_ + half * 64);
        uint32_t rb = (uint32_t)r * 256u;
        uint32_t rx = (uint32_t)(r & 7);
        float s = 0.f;
        #pragma unroll
        for (int i = 0; i < 8; i++) {
            float4 v0 = wr[2 * i], v1 = wr[2 * i + 1];
            s += v0.x * v0.x + v0.y * v0.y + v0.z * v0.z + v0.w * v0.w;
            s += v1.x * v1.x + v1.y * v1.y + v1.z * v1.z + v1.w * v1.w;
            __half2 h0 = __floats2half2_rn(v0.x, v0.y);
            __half2 h1 = __floats2half2_rn(v0.z, v0.w);
            __half2 h2 = __floats2half2_rn(v1.x, v1.y);
            __half2 h3 = __floats2half2_rn(v1.z, v1.w);
            uint32_t chunk = (uint32_t)(half * 8 + i);
            uint32_t sw = rb + ((chunk ^ rx) << 4);
            *reinterpret_cast<uint4*>(smem + OFF_B_HI + sw) =
                make_uint4(*reinterpret_cast<uint32_t*>(&h0), *reinterpret_cast<uint32_t*>(&h1),
                           *reinterpret_cast<uint32_t*>(&h2), *reinterpret_cast<uint32_t*>(&h3));
        }
        s += __shfl_xor_sync(0xffffffffu, s, 1);
        if (half == 0) *reinterpret_cast<float*>(smem + OFF_INVW + r * 4) = rsqrtf(s);
    }

    __syncthreads();

    // ---- ldmatrix lane->address maps (validated in R6) --------------------
    const int a_row_in = lane & 15;
    const uint32_t a_sel = (uint32_t)(lane >> 4);
    const int b_cls_in = ((lane >> 4) << 3) | (lane & 7);
    const uint32_t b_sel = (uint32_t)((lane >> 3) & 1);

    uint32_t aAddrH[4], aAddrL[4], arx[4];
    #pragma unroll
    for (int fm = 0; fm < 4; fm++) {
        int arow = wm * 64 + fm * 16 + a_row_in;
        aAddrH[fm] = sb + OFF_A_HI + (uint32_t)arow * 256u;
        aAddrL[fm] = sb + OFF_A_LO + (uint32_t)arow * 256u;
        arx[fm] = (uint32_t)(arow & 7);
    }
    uint32_t bAddr[4], brx[4];
    #pragma unroll
    for (int j2 = 0; j2 < 4; j2++) {
        int brow = wn * 64 + j2 * 16 + b_cls_in;
        bAddr[j2] = sb + OFF_B_HI + (uint32_t)brow * 256u;
        brx[j2] = (uint32_t)(brow & 7);
    }

    float d[4][8][4];
    #pragma unroll
    for (int fm = 0; fm < 4; fm++)
        #pragma unroll
        for (int jn = 0; jn < 8; jn++)
            #pragma unroll
            for (int q = 0; q < 4; q++) d[fm][jn][q] = 0.f;

    // ---- mainloop: per k16-chunk, B loaded once, hi + lo passes -----------
    #pragma unroll
    for (int kk = 0; kk < 8; kk++) {
        uint32_t b[4][4];
        #pragma unroll
        for (int j2 = 0; j2 < 4; j2++) {
            uint32_t chunk = (uint32_t)kk * 2u + b_sel;
            ldsm4(b[j2], bAddr[j2] + ((chunk ^ brx[j2]) << 4));
        }
        uint32_t a[4][4];
        #pragma unroll
        for (int fm = 0; fm < 4; fm++) {
            uint32_t chunk = (uint32_t)kk * 2u + a_sel;
            ldsm4(a[fm], aAddrH[fm] + ((chunk ^ arx[fm]) << 4));
        }
        #pragma unroll
        for (int fm = 0; fm < 4; fm++)
            #pragma unroll
            for (int jn = 0; jn < 8; jn++)
                mma_f16(d[fm][jn], a[fm],
                        b[jn >> 1][(jn & 1) * 2], b[jn >> 1][(jn & 1) * 2 + 1]);
        #pragma unroll
        for (int fm = 0; fm < 4; fm++) {
            uint32_t chunk = (uint32_t)kk * 2u + a_sel;
            ldsm4(a[fm], aAddrL[fm] + ((chunk ^ arx[fm]) << 4));
        }
        #pragma unroll
        for (int fm = 0; fm < 4; fm++)
            #pragma unroll
            for (int jn = 0; jn < 8; jn++)
                mma_f16(d[fm][jn], a[fm],
                        b[jn >> 1][(jn & 1) * 2], b[jn >> 1][(jn & 1) * 2 + 1]);
    }

    // ---- epilogue ---------------------------------------------------------
    const int g = lane >> 2, t2 = (lane & 3) * 2;
    float* out_cos = out;
    float* out_mrg = out + BC_;
    float* out_ip  = out + 2 * BC_;

    #pragma unroll
    for (int fm = 0; fm < 4; fm++) {
        int bat0 = wm * 64 + fm * 16 + g;
        float if0 = *reinterpret_cast<float*>(smem + OFF_INVF + bat0 * 4);
        float if1 = *reinterpret_cast<float*>(smem + OFF_INVF + (bat0 + 8) * 4);
        size_t ro0 = (size_t)bat0 * C_;
        size_t ro1 = (size_t)(bat0 + 8) * C_;
        #pragma unroll
        for (int jn = 0; jn < 8; jn++) {
            int cl = wn * 64 + jn * 8 + t2;
            int cls = cbase + cl;
            if (cls < C_) {
                float2 iw = *reinterpret_cast<float2*>(smem + OFF_INVW + cl * 4);
                float ip0 = d[fm][jn][0], ip1 = d[fm][jn][1];
                float ip2 = d[fm][jn][2], ip3 = d[fm][jn][3];
                float c0 = ip0 * if0 * iw.x, c1 = ip1 * if0 * iw.y;
                float c2 = ip2 * if1 * iw.x, c3 = ip3 * if1 * iw.y;
                *reinterpret_cast<float2*>(&out_ip[ro0 + cls])  = make_float2(ip0, ip1);
                *reinterpret_cast<float2*>(&out_ip[ro1 + cls])  = make_float2(ip2, ip3);
                *reinterpret_cast<float2*>(&out_cos[ro0 + cls]) = make_float2(c0, c1);
                *reinterpret_cast<float2*>(&out_cos[ro1 + cls]) = make_float2(c2, c3);
                *reinterpret_cast<float2*>(&out_mrg[ro0 + cls]) =
                    make_float2(SCALE_F * c0, SCALE_F * c1);
                *reinterpret_cast<float2*>(&out_mrg[ro1 + cls]) =
                    make_float2(SCALE_F * c2, SCALE_F * c3);
            }
        }
    }
}

// ---------------------------------------------------------------------------
// Kernel 3: ground-truth margin fixup (256 entries), float math.
// ---------------------------------------------------------------------------
__global__ void fix_gt_kernel(const int* __restrict__ lab_raw,
                              const float* __restrict__ out_cos,
                              float* __restrict__ out_mrg) {
    __shared__ int s_is64;
    int tid = threadIdx.x;
    if (tid == 0) s_is64 = 1;
    __syncthreads();
    if (tid < 128 && lab_raw[2 * tid + 1] != 0) atomicExch(&s_is64, 0);
    __syncthreads();

    int c = s_is64 ? lab_raw[2 * tid] : lab_raw[tid];
    size_t idx = (size_t)tid * C_ + c;
    float cg = out_cos[idx];

    float x = fminf(fmaxf(cg, -1.0f), 1.0f);
    const float thresh = -0.87758256189037271612f;     // -cos(0.5)
    float m;
    if (cg > thresh) m = cosf(acosf(x) + 0.5f);
    else             m = x - 0.5f * 0.47942553860420300027f;  // x - 0.5*sin(0.5)
    out_mrg[idx] = SCALE_F * m;
}

// ---------------------------------------------------------------------------
extern "C" void kernel_launch(void* const* d_in, const int* in_sizes, int n_in,
                              void* d_out, int out_size) {
    const float* feat = (const float*)d_in[0];
    const float* w    = (const float*)d_in[1];
    const int*   lab  = (const int*)d_in[2];
    float* out = (float*)d_out;

    prep_feat_kernel<<<32, 256>>>(feat);

    cudaFuncSetAttribute(arcface_hmma_kernel,
                         cudaFuncAttributeMaxDynamicSharedMemorySize, SMEM_TOTAL);
    int ntiles = (C_ + 127) / 128;   // 782
    arcface_hmma_kernel<<<ntiles, 256, SMEM_TOTAL>>>(w, out);

    fix_gt_kernel<<<1, 256>>>(lab, out, out + BC_);
}